// round 13
// baseline (speedup 1.0000x reference)
#include <cuda_runtime.h>

#define N_NODES 100000
#define N_EDGES 1600000
#define IN_DIM 128
#define HID 32
#define BN_EPS 1e-5f
#define CAP 96   // max in-degree capacity (Poisson(16); P(deg>=96) ~ 1e-46); %4==0

// ---- scratch (static device globals; no allocation allowed) ----
__device__ __align__(128) int   g_cnt[N_NODES];
__device__ __align__(128) int   g_slots[N_NODES * CAP];
__device__ __align__(128) float g_hs1[N_NODES * HID];
__device__ __align__(128) float g_z1[N_NODES * HID];
__device__ __align__(128) float g_hs2[N_NODES * HID];
__device__ float g_sums[64];   // [0:32) sum, [32:64) sumsq

// ---------------------------------------------------------------
__global__ void k_init() {
    int i = blockIdx.x * blockDim.x + threadIdx.x;
    if (i < N_NODES) g_cnt[i] = 0;
    if (i < 64) g_sums[i] = 0.0f;
}

__global__ void k_fill(const int* __restrict__ src, const int* __restrict__ dst) {
    int t = blockIdx.x * blockDim.x + threadIdx.x;
    int e0 = t * 4;
    if (e0 >= N_EDGES) return;
    int4 d4 = *(const int4*)&dst[e0];
    int4 s4 = *(const int4*)&src[e0];
    int pos;
    pos = atomicAdd(&g_cnt[d4.x], 1); if (pos < CAP) g_slots[d4.x * CAP + pos] = s4.x;
    pos = atomicAdd(&g_cnt[d4.y], 1); if (pos < CAP) g_slots[d4.y * CAP + pos] = s4.y;
    pos = atomicAdd(&g_cnt[d4.z], 1); if (pos < CAP) g_slots[d4.z * CAP + pos] = s4.z;
    pos = atomicAdd(&g_cnt[d4.w], 1); if (pos < CAP) g_slots[d4.w * CAP + pos] = s4.w;
}

// ---------------------------------------------------------------
// 3) GEMM1: hs1[r] = (x[r] @ W1) * dinv[r]   (direct-x read, W in smem)
__global__ void __launch_bounds__(256) k_gemm1(const float* __restrict__ x,
                                               const float* __restrict__ W1) {
    __shared__ float Ws[IN_DIM * HID];   // 16KB, [k][c]
    int tid = threadIdx.x;
    int rowbase = blockIdx.x * 128;
    int cg = tid & 7;
    int rg = tid >> 3;

    for (int i = tid; i < IN_DIM * HID / 4; i += 256)
        ((float4*)Ws)[i] = ((const float4*)W1)[i];
    __syncthreads();

    const float* xp[4];
    #pragma unroll
    for (int ri = 0; ri < 4; ri++) {
        int r = rowbase + rg * 4 + ri;
        xp[ri] = x + (size_t)min(r, N_NODES - 1) * IN_DIM;
    }

    float acc[4][4] = {};
    #pragma unroll 2
    for (int kq = 0; kq < IN_DIM / 4; kq++) {
        float4 a0 = *(const float4*)&xp[0][kq * 4];
        float4 a1 = *(const float4*)&xp[1][kq * 4];
        float4 a2 = *(const float4*)&xp[2][kq * 4];
        float4 a3 = *(const float4*)&xp[3][kq * 4];
        float4 w0 = *(const float4*)&Ws[(kq * 4 + 0) * HID + cg * 4];
        float4 w1 = *(const float4*)&Ws[(kq * 4 + 1) * HID + cg * 4];
        float4 w2 = *(const float4*)&Ws[(kq * 4 + 2) * HID + cg * 4];
        float4 w3 = *(const float4*)&Ws[(kq * 4 + 3) * HID + cg * 4];
        #pragma unroll
        for (int c = 0; c < 4; c++) {
            float wc0 = (&w0.x)[c], wc1 = (&w1.x)[c], wc2 = (&w2.x)[c], wc3 = (&w3.x)[c];
            acc[0][c] += a0.x * wc0 + a0.y * wc1 + a0.z * wc2 + a0.w * wc3;
            acc[1][c] += a1.x * wc0 + a1.y * wc1 + a1.z * wc2 + a1.w * wc3;
            acc[2][c] += a2.x * wc0 + a2.y * wc1 + a2.z * wc2 + a2.w * wc3;
            acc[3][c] += a3.x * wc0 + a3.y * wc1 + a3.z * wc2 + a3.w * wc3;
        }
    }

    #pragma unroll
    for (int ri = 0; ri < 4; ri++) {
        int r = rowbase + rg * 4 + ri;
        if (r < N_NODES) {
            float dinv = rsqrtf(1.0f + (float)g_cnt[r]);
            float4 v = make_float4(acc[ri][0] * dinv, acc[ri][1] * dinv,
                                   acc[ri][2] * dinv, acc[ri][3] * dinv);
            *(float4*)&g_hs1[(size_t)r * HID + cg * 4] = v;
        }
    }
}

// ---------------------------------------------------------------
// pull body: one warp = 4 nodes (8-lane group per node). Inner loop 2-way
// unrolled with dual accumulators -> two independent gather/FADD chains.
__device__ __forceinline__ float4 pull4(const float* __restrict__ hs, int wbase,
                                        int lane, int* __restrict__ sidx /*4*CAP*/) {
    int sw = lane >> 3;
    int gl = lane & 7;
    int n = wbase + sw;
    int cnt = g_cnt[n];
    int rem = min(cnt, CAP);
    const int* base = &g_slots[(size_t)n * CAP];
    int* sg = sidx + sw * CAP;

    for (int jb = 0; jb < rem; jb += 32) {
        int p = jb + gl * 4;
        if (p < rem) *(int4*)&sg[p] = *(const int4*)&base[p];
    }
    __syncwarp();

    float4 acc = *(const float4*)&hs[(size_t)n * HID + gl * 4];   // self loop
    float4 acc2 = make_float4(0.f, 0.f, 0.f, 0.f);

    int j = 0;
    for (; j + 2 <= rem; j += 2) {
        int s0 = sg[j];
        int s1 = sg[j + 1];
        float4 v0 = *(const float4*)&hs[(size_t)s0 * HID + gl * 4];
        float4 v1 = *(const float4*)&hs[(size_t)s1 * HID + gl * 4];
        acc.x += v0.x;  acc.y += v0.y;  acc.z += v0.z;  acc.w += v0.w;
        acc2.x += v1.x; acc2.y += v1.y; acc2.z += v1.z; acc2.w += v1.w;
    }
    if (j < rem) {
        int s = sg[j];
        float4 v = *(const float4*)&hs[(size_t)s * HID + gl * 4];
        acc.x += v.x; acc.y += v.y; acc.z += v.z; acc.w += v.w;
    }
    acc.x += acc2.x; acc.y += acc2.y; acc.z += acc2.z; acc.w += acc2.w;

    float dinv = rsqrtf(1.0f + (float)cnt);
    acc.x *= dinv; acc.y *= dinv; acc.z *= dinv; acc.w *= dinv;
    return acc;
}

// pull1 + fused BN statistics over v = z1 + b1.
// Grid is exact: 3125 blocks * 8 warps * 4 nodes = 100000 = N_NODES.
__global__ void k_pull1(const float* __restrict__ b1) {
    __shared__ __align__(16) int sidx[8][4 * CAP];    // 12KB
    __shared__ float red_s[8][4][33];                 // padded: stride-33 conflict-free
    __shared__ float red_q[8][4][33];
    int warp = (blockIdx.x * blockDim.x + threadIdx.x) >> 5;
    int lane = threadIdx.x & 31;
    int wslot = threadIdx.x >> 5;
    int sw = lane >> 3, gl = lane & 7;
    int wbase = warp * 4;

    float4 r = pull4(g_hs1, wbase, lane, sidx[wslot]);
    int n = wbase + sw;
    *(float4*)&g_z1[(size_t)n * HID + gl * 4] = r;

    // stats staging: v = r + b1
    float4 bb = *(const float4*)&b1[gl * 4];
    float vx = r.x + bb.x, vy = r.y + bb.y, vz = r.z + bb.z, vw = r.w + bb.w;
    red_s[wslot][sw][gl * 4 + 0] = vx;  red_q[wslot][sw][gl * 4 + 0] = vx * vx;
    red_s[wslot][sw][gl * 4 + 1] = vy;  red_q[wslot][sw][gl * 4 + 1] = vy * vy;
    red_s[wslot][sw][gl * 4 + 2] = vz;  red_q[wslot][sw][gl * 4 + 2] = vz * vz;
    red_s[wslot][sw][gl * 4 + 3] = vw;  red_q[wslot][sw][gl * 4 + 3] = vw * vw;
    __syncthreads();

    int tid = threadIdx.x;
    if (tid < 64) {
        int ch = tid & 31;
        bool sq = tid >= 32;
        const float* src = sq ? &red_q[0][0][0] : &red_s[0][0][0];
        float s = 0.f;
        #pragma unroll
        for (int i = 0; i < 32; i++)
            s += src[i * 33 + ch];
        atomicAdd(&g_sums[(sq ? 32 : 0) + ch], s);
    }
}

__global__ void k_pull2(const float* __restrict__ b2, float* __restrict__ out) {
    __shared__ __align__(16) int sidx[8][4 * CAP];
    int warp = (blockIdx.x * blockDim.x + threadIdx.x) >> 5;
    int lane = threadIdx.x & 31;
    int wslot = threadIdx.x >> 5;
    int wbase = warp * 4;
    if (wbase >= N_NODES) return;
    float4 r = pull4(g_hs2, wbase, lane, sidx[wslot]);
    float4 bb = *(const float4*)&b2[(lane & 7) * 4];
    r.x += bb.x; r.y += bb.y; r.z += bb.z; r.w += bb.w;
    int n = wbase + (lane >> 3);
    *(float4*)&out[(size_t)n * HID + (lane & 7) * 4] = r;
}

// ---------------------------------------------------------------
// 7) GEMM2 (bnfin fused): z = relu(BN(z1 + b1)); hs2 = (z@W2)*dinv
__global__ void k_gemm2(const float* __restrict__ b1, const float* __restrict__ gamma,
                        const float* __restrict__ beta, const float* __restrict__ W2) {
    __shared__ float Ws[HID * HID];
    __shared__ float Zs[128 * 36];
    __shared__ float sc_s[32], sh_s[32], bb_s[32];
    int tid = threadIdx.x;
    int rowbase = blockIdx.x * 128;

    if (tid < 32) {
        float mean = g_sums[tid] * (1.0f / N_NODES);
        float var = g_sums[32 + tid] * (1.0f / N_NODES) - mean * mean;
        var = fmaxf(var, 0.f);
        float sc = gamma[tid] * rsqrtf(var + BN_EPS);
        sc_s[tid] = sc;
        sh_s[tid] = beta[tid] - mean * sc;
        bb_s[tid] = b1[tid];
    }
    for (int i = tid; i < HID * HID / 4; i += 256)
        ((float4*)Ws)[i] = ((const float4*)W2)[i];
    __syncthreads();

    #pragma unroll
    for (int j = 0; j < 4; j++) {
        int idx = tid + j * 256;
        int r = idx >> 3, q = idx & 7;
        int gr = rowbase + r;
        float4 v = make_float4(0.f, 0.f, 0.f, 0.f);
        if (gr < N_NODES) {
            float4 a = *(const float4*)&g_z1[(size_t)gr * HID + q * 4];
            int c = q * 4;
            v.x = fmaxf(fmaf(a.x + bb_s[c + 0], sc_s[c + 0], sh_s[c + 0]), 0.f);
            v.y = fmaxf(fmaf(a.y + bb_s[c + 1], sc_s[c + 1], sh_s[c + 1]), 0.f);
            v.z = fmaxf(fmaf(a.z + bb_s[c + 2], sc_s[c + 2], sh_s[c + 2]), 0.f);
            v.w = fmaxf(fmaf(a.w + bb_s[c + 3], sc_s[c + 3], sh_s[c + 3]), 0.f);
        }
        *(float4*)&Zs[r * 36 + q * 4] = v;
    }
    __syncthreads();

    int cg = tid & 7, rg = tid >> 3;
    float acc[4][4] = {};
    #pragma unroll
    for (int k = 0; k < 32; k++) {
        float4 b4 = *(const float4*)&Ws[k * HID + cg * 4];
        #pragma unroll
        for (int ri = 0; ri < 4; ri++) {
            float a = Zs[(rg * 4 + ri) * 36 + k];
            acc[ri][0] += a * b4.x; acc[ri][1] += a * b4.y;
            acc[ri][2] += a * b4.z; acc[ri][3] += a * b4.w;
        }
    }
    #pragma unroll
    for (int ri = 0; ri < 4; ri++) {
        int r = rowbase + rg * 4 + ri;
        if (r < N_NODES) {
            float dinv = rsqrtf(1.0f + (float)g_cnt[r]);
            float4 v = make_float4(acc[ri][0] * dinv, acc[ri][1] * dinv,
                                   acc[ri][2] * dinv, acc[ri][3] * dinv);
            *(float4*)&g_hs2[(size_t)r * HID + cg * 4] = v;
        }
    }
}

// ---------------------------------------------------------------
extern "C" void kernel_launch(void* const* d_in, const int* in_sizes, int n_in,
                              void* d_out, int out_size) {
    const float* x     = (const float*)d_in[0];
    const int*   ei    = (const int*)d_in[1];   // int32
    const float* W1    = (const float*)d_in[2];
    const float* b1    = (const float*)d_in[3];
    const float* gamma = (const float*)d_in[4];
    const float* beta  = (const float*)d_in[5];
    const float* W2    = (const float*)d_in[6];
    const float* b2    = (const float*)d_in[7];
    float* out = (float*)d_out;

    const int* esrc = ei;
    const int* edst = ei + N_EDGES;

    int pull_blocks = (N_NODES / 4 * 32 + 255) / 256;   // 3125, exact

    k_init  <<<(N_NODES + 255) / 256, 256>>>();
    k_fill  <<<(N_EDGES / 4 + 255) / 256, 256>>>(esrc, edst);
    k_gemm1 <<<(N_NODES + 127) / 128, 256>>>(x, W1);
    k_pull1 <<<pull_blocks, 256>>>(b1);
    k_gemm2 <<<(N_NODES + 127) / 128, 256>>>(b1, gamma, beta, W2);
    k_pull2 <<<pull_blocks, 256>>>(b2, out);
}

// round 14
// speedup vs baseline: 1.3710x; 1.3710x over previous
#include <cuda_runtime.h>

#define N_NODES 100000
#define N_EDGES 1600000
#define IN_DIM 128
#define HID 32
#define BN_EPS 1e-5f
#define CAP 96   // max in-degree capacity (Poisson(16); P(deg>=96) ~ 1e-46); %4==0

// ---- scratch (static device globals; no allocation allowed) ----
__device__ __align__(128) int   g_cnt[N_NODES];
__device__ __align__(128) int   g_slots[N_NODES * CAP];
__device__ __align__(128) float g_hs1[N_NODES * HID];
__device__ __align__(128) float g_z1[N_NODES * HID];
__device__ __align__(128) float g_hs2[N_NODES * HID];
__device__ float g_sums[64];   // [0:32) sum, [32:64) sumsq

// ---------------------------------------------------------------
__global__ void k_init() {
    int i = blockIdx.x * blockDim.x + threadIdx.x;
    if (i < N_NODES) g_cnt[i] = 0;
    if (i < 64) g_sums[i] = 0.0f;
}

__global__ void k_fill(const int* __restrict__ src, const int* __restrict__ dst) {
    int t = blockIdx.x * blockDim.x + threadIdx.x;
    int e0 = t * 4;
    if (e0 >= N_EDGES) return;
    int4 d4 = *(const int4*)&dst[e0];
    int4 s4 = *(const int4*)&src[e0];
    int pos;
    pos = atomicAdd(&g_cnt[d4.x], 1); if (pos < CAP) g_slots[d4.x * CAP + pos] = s4.x;
    pos = atomicAdd(&g_cnt[d4.y], 1); if (pos < CAP) g_slots[d4.y * CAP + pos] = s4.y;
    pos = atomicAdd(&g_cnt[d4.z], 1); if (pos < CAP) g_slots[d4.z * CAP + pos] = s4.z;
    pos = atomicAdd(&g_cnt[d4.w], 1); if (pos < CAP) g_slots[d4.w * CAP + pos] = s4.w;
}

// ---------------------------------------------------------------
// 3) GEMM1 (round-11 staged version, occ-4 bound): hs1[r] = (x[r] @ W1) * dinv[r]
__global__ void __launch_bounds__(256, 4) k_gemm1(const float* __restrict__ x,
                                                  const float* __restrict__ W1) {
    __shared__ float Ws[IN_DIM * HID];   // 16KB
    __shared__ float Xs[128 * 36];       // 18KB padded
    int tid = threadIdx.x;
    int rowbase = blockIdx.x * 128;

    for (int i = tid; i < IN_DIM * HID / 4; i += 256)
        ((float4*)Ws)[i] = ((const float4*)W1)[i];

    int cg = tid & 7;
    int rg = tid >> 3;
    float acc[4][4] = {};

    for (int kb = 0; kb < IN_DIM; kb += 32) {
        __syncthreads();
        #pragma unroll
        for (int j = 0; j < 4; j++) {
            int idx = tid + j * 256;
            int r = idx >> 3, q = idx & 7;
            int gr = rowbase + r;
            float4 v = make_float4(0.f, 0.f, 0.f, 0.f);
            if (gr < N_NODES) v = *(const float4*)&x[(size_t)gr * IN_DIM + kb + q * 4];
            *(float4*)&Xs[r * 36 + q * 4] = v;
        }
        __syncthreads();
        #pragma unroll
        for (int k = 0; k < 32; k++) {
            float4 b4 = *(const float4*)&Ws[(kb + k) * HID + cg * 4];
            #pragma unroll
            for (int ri = 0; ri < 4; ri++) {
                float a = Xs[(rg * 4 + ri) * 36 + k];
                acc[ri][0] += a * b4.x; acc[ri][1] += a * b4.y;
                acc[ri][2] += a * b4.z; acc[ri][3] += a * b4.w;
            }
        }
    }
    #pragma unroll
    for (int ri = 0; ri < 4; ri++) {
        int r = rowbase + rg * 4 + ri;
        if (r < N_NODES) {
            float dinv = rsqrtf(1.0f + (float)g_cnt[r]);
            float4 v = make_float4(acc[ri][0] * dinv, acc[ri][1] * dinv,
                                   acc[ri][2] * dinv, acc[ri][3] * dinv);
            *(float4*)&g_hs1[(size_t)r * HID + cg * 4] = v;
        }
    }
}

// ---------------------------------------------------------------
// pull body (round-11, best measured — DO NOT TOUCH): one warp = 4 nodes,
// each 8-lane group owns one node end-to-end; single-accumulator loop.
__device__ __forceinline__ float4 pull4(const float* __restrict__ hs, int wbase,
                                        int lane, int* __restrict__ sidx /*4*CAP*/) {
    int sw = lane >> 3;
    int gl = lane & 7;
    int n = wbase + sw;
    int cnt = g_cnt[n];
    int rem = min(cnt, CAP);
    const int* base = &g_slots[(size_t)n * CAP];
    int* sg = sidx + sw * CAP;

    for (int jb = 0; jb < rem; jb += 32) {
        int p = jb + gl * 4;
        if (p < rem) *(int4*)&sg[p] = *(const int4*)&base[p];
    }
    __syncwarp();

    float4 acc = *(const float4*)&hs[(size_t)n * HID + gl * 4];   // self loop

    for (int j = 0; j < rem; j++) {
        int s = sg[j];
        float4 v = *(const float4*)&hs[(size_t)s * HID + gl * 4];
        acc.x += v.x; acc.y += v.y; acc.z += v.z; acc.w += v.w;
    }

    float dinv = rsqrtf(1.0f + (float)cnt);
    acc.x *= dinv; acc.y *= dinv; acc.z *= dinv; acc.w *= dinv;
    return acc;
}

__global__ void k_pull1() {
    __shared__ __align__(16) int sidx[8][4 * CAP];   // 12KB
    int warp = (blockIdx.x * blockDim.x + threadIdx.x) >> 5;
    int lane = threadIdx.x & 31;
    int wslot = threadIdx.x >> 5;
    int wbase = warp * 4;
    if (wbase >= N_NODES) return;
    float4 r = pull4(g_hs1, wbase, lane, sidx[wslot]);
    int n = wbase + (lane >> 3);
    *(float4*)&g_z1[(size_t)n * HID + (lane & 7) * 4] = r;
}

__global__ void k_pull2(const float* __restrict__ b2, float* __restrict__ out) {
    __shared__ __align__(16) int sidx[8][4 * CAP];
    int warp = (blockIdx.x * blockDim.x + threadIdx.x) >> 5;
    int lane = threadIdx.x & 31;
    int wslot = threadIdx.x >> 5;
    int wbase = warp * 4;
    if (wbase >= N_NODES) return;
    float4 r = pull4(g_hs2, wbase, lane, sidx[wslot]);
    float4 bb = *(const float4*)&b2[(lane & 7) * 4];
    r.x += bb.x; r.y += bb.y; r.z += bb.z; r.w += bb.w;
    int n = wbase + (lane >> 3);
    *(float4*)&out[(size_t)n * HID + (lane & 7) * 4] = r;
}

// ---------------------------------------------------------------
// 5) BN stats over v = z1 + b1 (vectorized: float4 per thread, 4 channels)
//    tid = rs*8 + q ; q = channel quad, rs = row slice.
__global__ void k_bnstats(const float* __restrict__ b1) {
    __shared__ float4 ss[256], sq[256];
    int tid = threadIdx.x;
    int q = tid & 7;      // channel quad 0..7
    int rs = tid >> 3;    // row slice 0..31
    int chunk = (N_NODES + gridDim.x - 1) / gridDim.x;
    int r0 = blockIdx.x * chunk;
    int r1 = min(r0 + chunk, N_NODES);
    float4 bb = *(const float4*)&b1[q * 4];
    float4 s = make_float4(0.f, 0.f, 0.f, 0.f);
    float4 s2 = make_float4(0.f, 0.f, 0.f, 0.f);
    for (int r = r0 + rs; r < r1; r += 32) {
        float4 v = *(const float4*)&g_z1[(size_t)r * HID + q * 4];
        v.x += bb.x; v.y += bb.y; v.z += bb.z; v.w += bb.w;
        s.x += v.x; s.y += v.y; s.z += v.z; s.w += v.w;
        s2.x += v.x * v.x; s2.y += v.y * v.y; s2.z += v.z * v.z; s2.w += v.w * v.w;
    }
    ss[tid] = s; sq[tid] = s2;
    __syncthreads();
    // reduce over rs (same q): strides 128,64,32,16,8
    #pragma unroll
    for (int off = 128; off >= 8; off >>= 1) {
        if (tid < off) {
            float4 a = ss[tid], b = ss[tid + off];
            a.x += b.x; a.y += b.y; a.z += b.z; a.w += b.w;
            ss[tid] = a;
            float4 c = sq[tid], d = sq[tid + off];
            c.x += d.x; c.y += d.y; c.z += d.z; c.w += d.w;
            sq[tid] = c;
        }
        __syncthreads();
    }
    if (tid < 8) {
        float4 a = ss[tid], c = sq[tid];
        atomicAdd(&g_sums[tid * 4 + 0], a.x);
        atomicAdd(&g_sums[tid * 4 + 1], a.y);
        atomicAdd(&g_sums[tid * 4 + 2], a.z);
        atomicAdd(&g_sums[tid * 4 + 3], a.w);
        atomicAdd(&g_sums[32 + tid * 4 + 0], c.x);
        atomicAdd(&g_sums[32 + tid * 4 + 1], c.y);
        atomicAdd(&g_sums[32 + tid * 4 + 2], c.z);
        atomicAdd(&g_sums[32 + tid * 4 + 3], c.w);
    }
}

// ---------------------------------------------------------------
// 7) GEMM2 (bnfin fused): z = relu(BN(z1 + b1)); hs2 = (z@W2)*dinv
__global__ void k_gemm2(const float* __restrict__ b1, const float* __restrict__ gamma,
                        const float* __restrict__ beta, const float* __restrict__ W2) {
    __shared__ float Ws[HID * HID];
    __shared__ float Zs[128 * 36];
    __shared__ float sc_s[32], sh_s[32], bb_s[32];
    int tid = threadIdx.x;
    int rowbase = blockIdx.x * 128;

    if (tid < 32) {
        float mean = g_sums[tid] * (1.0f / N_NODES);
        float var = g_sums[32 + tid] * (1.0f / N_NODES) - mean * mean;
        var = fmaxf(var, 0.f);
        float sc = gamma[tid] * rsqrtf(var + BN_EPS);
        sc_s[tid] = sc;
        sh_s[tid] = beta[tid] - mean * sc;
        bb_s[tid] = b1[tid];
    }
    for (int i = tid; i < HID * HID / 4; i += 256)
        ((float4*)Ws)[i] = ((const float4*)W2)[i];
    __syncthreads();

    #pragma unroll
    for (int j = 0; j < 4; j++) {
        int idx = tid + j * 256;
        int r = idx >> 3, q = idx & 7;
        int gr = rowbase + r;
        float4 v = make_float4(0.f, 0.f, 0.f, 0.f);
        if (gr < N_NODES) {
            float4 a = *(const float4*)&g_z1[(size_t)gr * HID + q * 4];
            int c = q * 4;
            v.x = fmaxf(fmaf(a.x + bb_s[c + 0], sc_s[c + 0], sh_s[c + 0]), 0.f);
            v.y = fmaxf(fmaf(a.y + bb_s[c + 1], sc_s[c + 1], sh_s[c + 1]), 0.f);
            v.z = fmaxf(fmaf(a.z + bb_s[c + 2], sc_s[c + 2], sh_s[c + 2]), 0.f);
            v.w = fmaxf(fmaf(a.w + bb_s[c + 3], sc_s[c + 3], sh_s[c + 3]), 0.f);
        }
        *(float4*)&Zs[r * 36 + q * 4] = v;
    }
    __syncthreads();

    int cg = tid & 7, rg = tid >> 3;
    float acc[4][4] = {};
    #pragma unroll
    for (int k = 0; k < 32; k++) {
        float4 b4 = *(const float4*)&Ws[k * HID + cg * 4];
        #pragma unroll
        for (int ri = 0; ri < 4; ri++) {
            float a = Zs[(rg * 4 + ri) * 36 + k];
            acc[ri][0] += a * b4.x; acc[ri][1] += a * b4.y;
            acc[ri][2] += a * b4.z; acc[ri][3] += a * b4.w;
        }
    }
    #pragma unroll
    for (int ri = 0; ri < 4; ri++) {
        int r = rowbase + rg * 4 + ri;
        if (r < N_NODES) {
            float dinv = rsqrtf(1.0f + (float)g_cnt[r]);
            float4 v = make_float4(acc[ri][0] * dinv, acc[ri][1] * dinv,
                                   acc[ri][2] * dinv, acc[ri][3] * dinv);
            *(float4*)&g_hs2[(size_t)r * HID + cg * 4] = v;
        }
    }
}

// ---------------------------------------------------------------
extern "C" void kernel_launch(void* const* d_in, const int* in_sizes, int n_in,
                              void* d_out, int out_size) {
    const float* x     = (const float*)d_in[0];
    const int*   ei    = (const int*)d_in[1];   // int32
    const float* W1    = (const float*)d_in[2];
    const float* b1    = (const float*)d_in[3];
    const float* gamma = (const float*)d_in[4];
    const float* beta  = (const float*)d_in[5];
    const float* W2    = (const float*)d_in[6];
    const float* b2    = (const float*)d_in[7];
    float* out = (float*)d_out;

    const int* esrc = ei;
    const int* edst = ei + N_EDGES;

    int pull_blocks = (N_NODES / 4 * 32 + 255) / 256;   // 3125

    k_init   <<<(N_NODES + 255) / 256, 256>>>();
    k_fill   <<<(N_EDGES / 4 + 255) / 256, 256>>>(esrc, edst);
    k_gemm1  <<<(N_NODES + 127) / 128, 256>>>(x, W1);
    k_pull1  <<<pull_blocks, 256>>>();
    k_bnstats<<<592, 256>>>(b1);
    k_gemm2  <<<(N_NODES + 127) / 128, 256>>>(b1, gamma, beta, W2);
    k_pull2  <<<pull_blocks, 256>>>(b2, out);
}

// round 15
// speedup vs baseline: 1.4670x; 1.0700x over previous
#include <cuda_runtime.h>

#define N_NODES 100000
#define N_EDGES 1600000
#define IN_DIM 128
#define HID 32
#define BN_EPS 1e-5f
#define CAP 96   // max in-degree capacity (Poisson(16); P(deg>=96) ~ 1e-46); %4==0

// ---- scratch (static device globals; no allocation allowed) ----
__device__ __align__(128) int   g_cnt[N_NODES];
__device__ __align__(128) int   g_slots[N_NODES * CAP];
__device__ __align__(128) float g_hs1[N_NODES * HID];
__device__ __align__(128) float g_z1[N_NODES * HID];
__device__ __align__(128) float g_hs2[N_NODES * HID];
__device__ float g_sums[64];   // [0:32) sum, [32:64) sumsq

// ---------------------------------------------------------------
__global__ void k_init() {
    int i = blockIdx.x * blockDim.x + threadIdx.x;
    if (i < N_NODES) g_cnt[i] = 0;
    if (i < 64) g_sums[i] = 0.0f;
}

__global__ void k_fill(const int* __restrict__ src, const int* __restrict__ dst) {
    int t = blockIdx.x * blockDim.x + threadIdx.x;
    int e0 = t * 4;
    if (e0 >= N_EDGES) return;
    int4 d4 = *(const int4*)&dst[e0];
    int4 s4 = *(const int4*)&src[e0];
    int pos;
    pos = atomicAdd(&g_cnt[d4.x], 1); if (pos < CAP) g_slots[d4.x * CAP + pos] = s4.x;
    pos = atomicAdd(&g_cnt[d4.y], 1); if (pos < CAP) g_slots[d4.y * CAP + pos] = s4.y;
    pos = atomicAdd(&g_cnt[d4.z], 1); if (pos < CAP) g_slots[d4.z * CAP + pos] = s4.z;
    pos = atomicAdd(&g_cnt[d4.w], 1); if (pos < CAP) g_slots[d4.w * CAP + pos] = s4.w;
}

// ---------------------------------------------------------------
// 3) GEMM1 (round-11 staged version, occ-4 bound): hs1[r] = (x[r] @ W1) * dinv[r]
__global__ void __launch_bounds__(256, 4) k_gemm1(const float* __restrict__ x,
                                                  const float* __restrict__ W1) {
    __shared__ float Ws[IN_DIM * HID];   // 16KB
    __shared__ float Xs[128 * 36];       // 18KB padded
    int tid = threadIdx.x;
    int rowbase = blockIdx.x * 128;

    for (int i = tid; i < IN_DIM * HID / 4; i += 256)
        ((float4*)Ws)[i] = ((const float4*)W1)[i];

    int cg = tid & 7;
    int rg = tid >> 3;
    float acc[4][4] = {};

    for (int kb = 0; kb < IN_DIM; kb += 32) {
        __syncthreads();
        #pragma unroll
        for (int j = 0; j < 4; j++) {
            int idx = tid + j * 256;
            int r = idx >> 3, q = idx & 7;
            int gr = rowbase + r;
            float4 v = make_float4(0.f, 0.f, 0.f, 0.f);
            if (gr < N_NODES) v = *(const float4*)&x[(size_t)gr * IN_DIM + kb + q * 4];
            *(float4*)&Xs[r * 36 + q * 4] = v;
        }
        __syncthreads();
        #pragma unroll
        for (int k = 0; k < 32; k++) {
            float4 b4 = *(const float4*)&Ws[(kb + k) * HID + cg * 4];
            #pragma unroll
            for (int ri = 0; ri < 4; ri++) {
                float a = Xs[(rg * 4 + ri) * 36 + k];
                acc[ri][0] += a * b4.x; acc[ri][1] += a * b4.y;
                acc[ri][2] += a * b4.z; acc[ri][3] += a * b4.w;
            }
        }
    }
    #pragma unroll
    for (int ri = 0; ri < 4; ri++) {
        int r = rowbase + rg * 4 + ri;
        if (r < N_NODES) {
            float dinv = rsqrtf(1.0f + (float)g_cnt[r]);
            float4 v = make_float4(acc[ri][0] * dinv, acc[ri][1] * dinv,
                                   acc[ri][2] * dinv, acc[ri][3] * dinv);
            *(float4*)&g_hs1[(size_t)r * HID + cg * 4] = v;
        }
    }
}

// ---------------------------------------------------------------
// pull body (round-11, best measured — UNTOUCHED): one warp = 4 nodes,
// each 8-lane group owns one node end-to-end; single-accumulator loop.
__device__ __forceinline__ float4 pull4(const float* __restrict__ hs, int wbase,
                                        int lane, int* __restrict__ sidx /*4*CAP*/) {
    int sw = lane >> 3;
    int gl = lane & 7;
    int n = wbase + sw;
    int cnt = g_cnt[n];
    int rem = min(cnt, CAP);
    const int* base = &g_slots[(size_t)n * CAP];
    int* sg = sidx + sw * CAP;

    for (int jb = 0; jb < rem; jb += 32) {
        int p = jb + gl * 4;
        if (p < rem) *(int4*)&sg[p] = *(const int4*)&base[p];
    }
    __syncwarp();

    float4 acc = *(const float4*)&hs[(size_t)n * HID + gl * 4];   // self loop

    for (int j = 0; j < rem; j++) {
        int s = sg[j];
        float4 v = *(const float4*)&hs[(size_t)s * HID + gl * 4];
        acc.x += v.x; acc.y += v.y; acc.z += v.z; acc.w += v.w;
    }

    float dinv = rsqrtf(1.0f + (float)cnt);
    acc.x *= dinv; acc.y *= dinv; acc.z *= dinv; acc.w *= dinv;
    return acc;
}

// pull1 + fused BN statistics over v = z1 + b1.
// Grid is exact: 3125 blocks * 8 warps * 4 nodes = 100000 = N_NODES,
// so every thread reaches __syncthreads (no early returns).
__global__ void k_pull1(const float* __restrict__ b1) {
    __shared__ __align__(16) int sidx[8][4 * CAP];    // 12KB
    __shared__ float red_s[32][33];                   // stride-33: conflict-free
    __shared__ float red_q[32][33];
    int warp = (blockIdx.x * blockDim.x + threadIdx.x) >> 5;
    int lane = threadIdx.x & 31;
    int wslot = threadIdx.x >> 5;
    int sw = lane >> 3, gl = lane & 7;
    int wbase = warp * 4;

    float4 r = pull4(g_hs1, wbase, lane, sidx[wslot]);
    int n = wbase + sw;
    *(float4*)&g_z1[(size_t)n * HID + gl * 4] = r;

    // stats staging: v = r + b1 ; row = node slot within block (0..31)
    int slot = wslot * 4 + sw;
    float4 bb = *(const float4*)&b1[gl * 4];
    float vx = r.x + bb.x, vy = r.y + bb.y, vz = r.z + bb.z, vw = r.w + bb.w;
    red_s[slot][gl * 4 + 0] = vx;  red_q[slot][gl * 4 + 0] = vx * vx;
    red_s[slot][gl * 4 + 1] = vy;  red_q[slot][gl * 4 + 1] = vy * vy;
    red_s[slot][gl * 4 + 2] = vz;  red_q[slot][gl * 4 + 2] = vz * vz;
    red_s[slot][gl * 4 + 3] = vw;  red_q[slot][gl * 4 + 3] = vw * vw;
    __syncthreads();

    int tid = threadIdx.x;
    if (tid < 64) {
        int ch = tid & 31;
        const float (*src)[33] = (tid >= 32) ? red_q : red_s;
        float s = 0.f;
        #pragma unroll
        for (int i = 0; i < 32; i++)
            s += src[i][ch];
        atomicAdd(&g_sums[(tid >= 32 ? 32 : 0) + ch], s);
    }
}

__global__ void k_pull2(const float* __restrict__ b2, float* __restrict__ out) {
    __shared__ __align__(16) int sidx[8][4 * CAP];
    int warp = (blockIdx.x * blockDim.x + threadIdx.x) >> 5;
    int lane = threadIdx.x & 31;
    int wslot = threadIdx.x >> 5;
    int wbase = warp * 4;
    if (wbase >= N_NODES) return;
    float4 r = pull4(g_hs2, wbase, lane, sidx[wslot]);
    float4 bb = *(const float4*)&b2[(lane & 7) * 4];
    r.x += bb.x; r.y += bb.y; r.z += bb.z; r.w += bb.w;
    int n = wbase + (lane >> 3);
    *(float4*)&out[(size_t)n * HID + (lane & 7) * 4] = r;
}

// ---------------------------------------------------------------
// 7) GEMM2 (bnfin fused): z = relu(BN(z1 + b1)); hs2 = (z@W2)*dinv
__global__ void k_gemm2(const float* __restrict__ b1, const float* __restrict__ gamma,
                        const float* __restrict__ beta, const float* __restrict__ W2) {
    __shared__ float Ws[HID * HID];
    __shared__ float Zs[128 * 36];
    __shared__ float sc_s[32], sh_s[32], bb_s[32];
    int tid = threadIdx.x;
    int rowbase = blockIdx.x * 128;

    if (tid < 32) {
        float mean = g_sums[tid] * (1.0f / N_NODES);
        float var = g_sums[32 + tid] * (1.0f / N_NODES) - mean * mean;
        var = fmaxf(var, 0.f);
        float sc = gamma[tid] * rsqrtf(var + BN_EPS);
        sc_s[tid] = sc;
        sh_s[tid] = beta[tid] - mean * sc;
        bb_s[tid] = b1[tid];
    }
    for (int i = tid; i < HID * HID / 4; i += 256)
        ((float4*)Ws)[i] = ((const float4*)W2)[i];
    __syncthreads();

    #pragma unroll
    for (int j = 0; j < 4; j++) {
        int idx = tid + j * 256;
        int r = idx >> 3, q = idx & 7;
        int gr = rowbase + r;
        float4 v = make_float4(0.f, 0.f, 0.f, 0.f);
        if (gr < N_NODES) {
            float4 a = *(const float4*)&g_z1[(size_t)gr * HID + q * 4];
            int c = q * 4;
            v.x = fmaxf(fmaf(a.x + bb_s[c + 0], sc_s[c + 0], sh_s[c + 0]), 0.f);
            v.y = fmaxf(fmaf(a.y + bb_s[c + 1], sc_s[c + 1], sh_s[c + 1]), 0.f);
            v.z = fmaxf(fmaf(a.z + bb_s[c + 2], sc_s[c + 2], sh_s[c + 2]), 0.f);
            v.w = fmaxf(fmaf(a.w + bb_s[c + 3], sc_s[c + 3], sh_s[c + 3]), 0.f);
        }
        *(float4*)&Zs[r * 36 + q * 4] = v;
    }
    __syncthreads();

    int cg = tid & 7, rg = tid >> 3;
    float acc[4][4] = {};
    #pragma unroll
    for (int k = 0; k < 32; k++) {
        float4 b4 = *(const float4*)&Ws[k * HID + cg * 4];
        #pragma unroll
        for (int ri = 0; ri < 4; ri++) {
            float a = Zs[(rg * 4 + ri) * 36 + k];
            acc[ri][0] += a * b4.x; acc[ri][1] += a * b4.y;
            acc[ri][2] += a * b4.z; acc[ri][3] += a * b4.w;
        }
    }
    #pragma unroll
    for (int ri = 0; ri < 4; ri++) {
        int r = rowbase + rg * 4 + ri;
        if (r < N_NODES) {
            float dinv = rsqrtf(1.0f + (float)g_cnt[r]);
            float4 v = make_float4(acc[ri][0] * dinv, acc[ri][1] * dinv,
                                   acc[ri][2] * dinv, acc[ri][3] * dinv);
            *(float4*)&g_hs2[(size_t)r * HID + cg * 4] = v;
        }
    }
}

// ---------------------------------------------------------------
extern "C" void kernel_launch(void* const* d_in, const int* in_sizes, int n_in,
                              void* d_out, int out_size) {
    const float* x     = (const float*)d_in[0];
    const int*   ei    = (const int*)d_in[1];   // int32
    const float* W1    = (const float*)d_in[2];
    const float* b1    = (const float*)d_in[3];
    const float* gamma = (const float*)d_in[4];
    const float* beta  = (const float*)d_in[5];
    const float* W2    = (const float*)d_in[6];
    const float* b2    = (const float*)d_in[7];
    float* out = (float*)d_out;

    const int* esrc = ei;
    const int* edst = ei + N_EDGES;

    int pull_blocks = (N_NODES / 4 * 32 + 255) / 256;   // 3125, exact

    k_init  <<<(N_NODES + 255) / 256, 256>>>();
    k_fill  <<<(N_EDGES / 4 + 255) / 256, 256>>>(esrc, edst);
    k_gemm1 <<<(N_NODES + 127) / 128, 256>>>(x, W1);
    k_pull1 <<<pull_blocks, 256>>>(b1);
    k_gemm2 <<<(N_NODES + 127) / 128, 256>>>(b1, gamma, beta, W2);
    k_pull2 <<<pull_blocks, 256>>>(b2, out);
}

// round 16
// speedup vs baseline: 1.5617x; 1.0646x over previous
#include <cuda_runtime.h>

#define N_NODES 100000
#define N_EDGES 1600000
#define IN_DIM 128
#define HID 32
#define BN_EPS 1e-5f
#define CAP 96   // max in-degree capacity (Poisson(16); P(deg>=96) ~ 1e-46); %4==0

// ---- scratch (static device globals; no allocation allowed) ----
// Self-cleaning invariant: g_cnt and g_sums are zero at every kernel_launch
// entry (zero-initialized at load; pull2 re-zeroes them after last use).
__device__ __align__(128) int   g_cnt[N_NODES];
__device__ __align__(128) int   g_slots[N_NODES * CAP];
__device__ __align__(128) float g_hs1[N_NODES * HID];
__device__ __align__(128) float g_z1[N_NODES * HID];
__device__ __align__(128) float g_hs2[N_NODES * HID];
__device__ float g_sums[64];   // [0:32) sum, [32:64) sumsq

// ---------------------------------------------------------------
// 1) fused fill + gemm1_raw. Independent tasks striped across blocks:
//    bid%3==0 -> gemm1 (782 blocks), else -> fill (1563 blocks).
//    gemm1 writes UNSCALED x@W1 (dinv applied by k_scale afterwards).
__global__ void __launch_bounds__(256, 4) k_fillgemm(const float* __restrict__ x,
                                                     const float* __restrict__ W1,
                                                     const int* __restrict__ src,
                                                     const int* __restrict__ dst) {
    __shared__ float Ws[IN_DIM * HID];   // 16KB
    __shared__ float Xs[128 * 36];       // 18KB padded
    int bid = blockIdx.x;
    int tid = threadIdx.x;

    if (bid % 3 != 0) {
        // ---- fill task: 4 edges per thread ----
        int frank = (bid / 3) * 2 + (bid % 3) - 1;       // 0..1562
        int e0 = (frank * 256 + tid) * 4;
        if (e0 >= N_EDGES) return;
        int4 d4 = *(const int4*)&dst[e0];
        int4 s4 = *(const int4*)&src[e0];
        int pos;
        pos = atomicAdd(&g_cnt[d4.x], 1); if (pos < CAP) g_slots[d4.x * CAP + pos] = s4.x;
        pos = atomicAdd(&g_cnt[d4.y], 1); if (pos < CAP) g_slots[d4.y * CAP + pos] = s4.y;
        pos = atomicAdd(&g_cnt[d4.z], 1); if (pos < CAP) g_slots[d4.z * CAP + pos] = s4.z;
        pos = atomicAdd(&g_cnt[d4.w], 1); if (pos < CAP) g_slots[d4.w * CAP + pos] = s4.w;
        return;
    }

    // ---- gemm1 task (round-11 body, no dinv) ----
    int rowbase = (bid / 3) * 128;

    for (int i = tid; i < IN_DIM * HID / 4; i += 256)
        ((float4*)Ws)[i] = ((const float4*)W1)[i];

    int cg = tid & 7;
    int rg = tid >> 3;
    float acc[4][4] = {};

    for (int kb = 0; kb < IN_DIM; kb += 32) {
        __syncthreads();
        #pragma unroll
        for (int j = 0; j < 4; j++) {
            int idx = tid + j * 256;
            int r = idx >> 3, q = idx & 7;
            int gr = rowbase + r;
            float4 v = make_float4(0.f, 0.f, 0.f, 0.f);
            if (gr < N_NODES) v = *(const float4*)&x[(size_t)gr * IN_DIM + kb + q * 4];
            *(float4*)&Xs[r * 36 + q * 4] = v;
        }
        __syncthreads();
        #pragma unroll
        for (int k = 0; k < 32; k++) {
            float4 b4 = *(const float4*)&Ws[(kb + k) * HID + cg * 4];
            #pragma unroll
            for (int ri = 0; ri < 4; ri++) {
                float a = Xs[(rg * 4 + ri) * 36 + k];
                acc[ri][0] += a * b4.x; acc[ri][1] += a * b4.y;
                acc[ri][2] += a * b4.z; acc[ri][3] += a * b4.w;
            }
        }
    }
    #pragma unroll
    for (int ri = 0; ri < 4; ri++) {
        int r = rowbase + rg * 4 + ri;
        if (r < N_NODES) {
            float4 v = make_float4(acc[ri][0], acc[ri][1], acc[ri][2], acc[ri][3]);
            *(float4*)&g_hs1[(size_t)r * HID + cg * 4] = v;
        }
    }
}

// 2) scale: hs1[r] *= dinv[r]  (needs fill + gemm1 complete)
__global__ void k_scale() {
    int i = blockIdx.x * blockDim.x + threadIdx.x;   // one float4 per thread
    if (i >= N_NODES * 8) return;
    int r = i >> 3, q = i & 7;
    float dinv = rsqrtf(1.0f + (float)g_cnt[r]);
    float4 v = *(const float4*)&g_hs1[(size_t)r * HID + q * 4];
    v.x *= dinv; v.y *= dinv; v.z *= dinv; v.w *= dinv;
    *(float4*)&g_hs1[(size_t)r * HID + q * 4] = v;
}

// ---------------------------------------------------------------
// pull body (round-11, best measured — UNTOUCHED)
__device__ __forceinline__ float4 pull4(const float* __restrict__ hs, int wbase,
                                        int lane, int* __restrict__ sidx /*4*CAP*/) {
    int sw = lane >> 3;
    int gl = lane & 7;
    int n = wbase + sw;
    int cnt = g_cnt[n];
    int rem = min(cnt, CAP);
    const int* base = &g_slots[(size_t)n * CAP];
    int* sg = sidx + sw * CAP;

    for (int jb = 0; jb < rem; jb += 32) {
        int p = jb + gl * 4;
        if (p < rem) *(int4*)&sg[p] = *(const int4*)&base[p];
    }
    __syncwarp();

    float4 acc = *(const float4*)&hs[(size_t)n * HID + gl * 4];   // self loop

    for (int j = 0; j < rem; j++) {
        int s = sg[j];
        float4 v = *(const float4*)&hs[(size_t)s * HID + gl * 4];
        acc.x += v.x; acc.y += v.y; acc.z += v.z; acc.w += v.w;
    }

    float dinv = rsqrtf(1.0f + (float)cnt);
    acc.x *= dinv; acc.y *= dinv; acc.z *= dinv; acc.w *= dinv;
    return acc;
}

// 3) pull1 + fused BN statistics (grid exact: 3125*8*4 = 100000 nodes)
__global__ void k_pull1(const float* __restrict__ b1) {
    __shared__ __align__(16) int sidx[8][4 * CAP];    // 12KB
    __shared__ float red_s[32][33];
    __shared__ float red_q[32][33];
    int warp = (blockIdx.x * blockDim.x + threadIdx.x) >> 5;
    int lane = threadIdx.x & 31;
    int wslot = threadIdx.x >> 5;
    int sw = lane >> 3, gl = lane & 7;
    int wbase = warp * 4;

    float4 r = pull4(g_hs1, wbase, lane, sidx[wslot]);
    int n = wbase + sw;
    *(float4*)&g_z1[(size_t)n * HID + gl * 4] = r;

    int slot = wslot * 4 + sw;
    float4 bb = *(const float4*)&b1[gl * 4];
    float vx = r.x + bb.x, vy = r.y + bb.y, vz = r.z + bb.z, vw = r.w + bb.w;
    red_s[slot][gl * 4 + 0] = vx;  red_q[slot][gl * 4 + 0] = vx * vx;
    red_s[slot][gl * 4 + 1] = vy;  red_q[slot][gl * 4 + 1] = vy * vy;
    red_s[slot][gl * 4 + 2] = vz;  red_q[slot][gl * 4 + 2] = vz * vz;
    red_s[slot][gl * 4 + 3] = vw;  red_q[slot][gl * 4 + 3] = vw * vw;
    __syncthreads();

    int tid = threadIdx.x;
    if (tid < 64) {
        int ch = tid & 31;
        const float (*srcp)[33] = (tid >= 32) ? red_q : red_s;
        float s = 0.f;
        #pragma unroll
        for (int i = 0; i < 32; i++)
            s += srcp[i][ch];
        atomicAdd(&g_sums[(tid >= 32 ? 32 : 0) + ch], s);
    }
}

// 5) pull2 + cleanup (restores g_cnt/g_sums zero-invariant for next call)
__global__ void k_pull2(const float* __restrict__ b2, float* __restrict__ out) {
    __shared__ __align__(16) int sidx[8][4 * CAP];
    int warp = (blockIdx.x * blockDim.x + threadIdx.x) >> 5;
    int lane = threadIdx.x & 31;
    int wslot = threadIdx.x >> 5;
    int wbase = warp * 4;
    if (wbase >= N_NODES) return;
    float4 r = pull4(g_hs2, wbase, lane, sidx[wslot]);
    float4 bb = *(const float4*)&b2[(lane & 7) * 4];
    r.x += bb.x; r.y += bb.y; r.z += bb.z; r.w += bb.w;
    int n = wbase + (lane >> 3);
    *(float4*)&out[(size_t)n * HID + (lane & 7) * 4] = r;

    // cleanup: each node's cnt read only by its owning group above
    if ((lane & 7) == 0) g_cnt[n] = 0;
    if (blockIdx.x == 0 && threadIdx.x < 64) g_sums[threadIdx.x] = 0.0f;
}

// ---------------------------------------------------------------
// 4) GEMM2 (bnfin fused): z = relu(BN(z1 + b1)); hs2 = (z@W2)*dinv
__global__ void k_gemm2(const float* __restrict__ b1, const float* __restrict__ gamma,
                        const float* __restrict__ beta, const float* __restrict__ W2) {
    __shared__ float Ws[HID * HID];
    __shared__ float Zs[128 * 36];
    __shared__ float sc_s[32], sh_s[32], bb_s[32];
    int tid = threadIdx.x;
    int rowbase = blockIdx.x * 128;

    if (tid < 32) {
        float mean = g_sums[tid] * (1.0f / N_NODES);
        float var = g_sums[32 + tid] * (1.0f / N_NODES) - mean * mean;
        var = fmaxf(var, 0.f);
        float sc = gamma[tid] * rsqrtf(var + BN_EPS);
        sc_s[tid] = sc;
        sh_s[tid] = beta[tid] - mean * sc;
        bb_s[tid] = b1[tid];
    }
    for (int i = tid; i < HID * HID / 4; i += 256)
        ((float4*)Ws)[i] = ((const float4*)W2)[i];
    __syncthreads();

    #pragma unroll
    for (int j = 0; j < 4; j++) {
        int idx = tid + j * 256;
        int r = idx >> 3, q = idx & 7;
        int gr = rowbase + r;
        float4 v = make_float4(0.f, 0.f, 0.f, 0.f);
        if (gr < N_NODES) {
            float4 a = *(const float4*)&g_z1[(size_t)gr * HID + q * 4];
            int c = q * 4;
            v.x = fmaxf(fmaf(a.x + bb_s[c + 0], sc_s[c + 0], sh_s[c + 0]), 0.f);
            v.y = fmaxf(fmaf(a.y + bb_s[c + 1], sc_s[c + 1], sh_s[c + 1]), 0.f);
            v.z = fmaxf(fmaf(a.z + bb_s[c + 2], sc_s[c + 2], sh_s[c + 2]), 0.f);
            v.w = fmaxf(fmaf(a.w + bb_s[c + 3], sc_s[c + 3], sh_s[c + 3]), 0.f);
        }
        *(float4*)&Zs[r * 36 + q * 4] = v;
    }
    __syncthreads();

    int cg = tid & 7, rg = tid >> 3;
    float acc[4][4] = {};
    #pragma unroll
    for (int k = 0; k < 32; k++) {
        float4 b4 = *(const float4*)&Ws[k * HID + cg * 4];
        #pragma unroll
        for (int ri = 0; ri < 4; ri++) {
            float a = Zs[(rg * 4 + ri) * 36 + k];
            acc[ri][0] += a * b4.x; acc[ri][1] += a * b4.y;
            acc[ri][2] += a * b4.z; acc[ri][3] += a * b4.w;
        }
    }
    #pragma unroll
    for (int ri = 0; ri < 4; ri++) {
        int r = rowbase + rg * 4 + ri;
        if (r < N_NODES) {
            float dinv = rsqrtf(1.0f + (float)g_cnt[r]);
            float4 v = make_float4(acc[ri][0] * dinv, acc[ri][1] * dinv,
                                   acc[ri][2] * dinv, acc[ri][3] * dinv);
            *(float4*)&g_hs2[(size_t)r * HID + cg * 4] = v;
        }
    }
}

// ---------------------------------------------------------------
extern "C" void kernel_launch(void* const* d_in, const int* in_sizes, int n_in,
                              void* d_out, int out_size) {
    const float* x     = (const float*)d_in[0];
    const int*   ei    = (const int*)d_in[1];   // int32
    const float* W1    = (const float*)d_in[2];
    const float* b1    = (const float*)d_in[3];
    const float* gamma = (const float*)d_in[4];
    const float* beta  = (const float*)d_in[5];
    const float* W2    = (const float*)d_in[6];
    const float* b2    = (const float*)d_in[7];
    float* out = (float*)d_out;

    const int* esrc = ei;
    const int* edst = ei + N_EDGES;

    int pull_blocks = (N_NODES / 4 * 32 + 255) / 256;   // 3125, exact
    int fg_blocks = 2345;                               // 782 gemm + 1563 fill

    k_fillgemm<<<fg_blocks, 256>>>(x, W1, esrc, edst);
    k_scale   <<<(N_NODES * 8 + 255) / 256, 256>>>();
    k_pull1   <<<pull_blocks, 256>>>(b1);
    k_gemm2   <<<(N_NODES + 127) / 128, 256>>>(b1, gamma, beta, W2);
    k_pull2   <<<pull_blocks, 256>>>(b2, out);
}